// round 4
// baseline (speedup 1.0000x reference)
#include <cuda_runtime.h>
#include <cuda_fp16.h>
#include <cstdint>

#define KDIM   256
#define BM     128
#define BN     256
#define BK     64
#define NCHUNK 4

#define A_STAGE_BYTES (BM * BK * 2)            // 16384
#define B_CHUNK_BYTES (BN * BK * 2)            // 32768
#define A_TOTAL       (2 * A_STAGE_BYTES)      // 32768
#define SMEM_TOTAL    (A_TOTAL + NCHUNK * B_CHUNK_BYTES)   // 163840

// W^T in fp16: g_Wt[n][k] = half(W[k][n])
__device__ __align__(256) __half g_Wt[KDIM * KDIM];

// ---------------- helpers ----------------
__device__ __forceinline__ uint32_t smem_u32(const void* p) {
    uint32_t a;
    asm("{ .reg .u64 t; cvta.to.shared.u64 t, %1; cvt.u32.u64 %0, t; }" : "=r"(a) : "l"(p));
    return a;
}
__device__ __forceinline__ void cp16(uint32_t dst, const void* src) {
    asm volatile("cp.async.cg.shared.global [%0], [%1], 16;" :: "r"(dst), "l"(src));
}
__device__ __forceinline__ void cp_commit() {
    asm volatile("cp.async.commit_group;" ::: "memory");
}
template <int N> __device__ __forceinline__ void cp_wait() {
    asm volatile("cp.async.wait_group %0;" :: "n"(N) : "memory");
}
#define LDSM4(r0, r1, r2, r3, a)                                                 \
    asm volatile("ldmatrix.sync.aligned.m8n8.x4.shared.b16 {%0,%1,%2,%3}, [%4];" \
                 : "=r"(r0), "=r"(r1), "=r"(r2), "=r"(r3) : "r"(a))

__device__ __forceinline__ void mma_fp16(float* d, const uint32_t* a,
                                         uint32_t b0, uint32_t b1) {
    asm volatile(
        "mma.sync.aligned.m16n8k16.row.col.f32.f16.f16.f32 "
        "{%0,%1,%2,%3}, {%4,%5,%6,%7}, {%8,%9}, {%0,%1,%2,%3};"
        : "+f"(d[0]), "+f"(d[1]), "+f"(d[2]), "+f"(d[3])
        : "r"(a[0]), "r"(a[1]), "r"(a[2]), "r"(a[3]), "r"(b0), "r"(b1));
}

// ---------------- prep: W[K,N] fp32 -> Wt[N,K] fp16 ----------------
__global__ void prep_wt_kernel(const float* __restrict__ W) {
    int n = blockIdx.x, k = threadIdx.x;
    g_Wt[n * KDIM + k] = __float2half_rn(W[k * KDIM + n]);
}

// ---------------- main GEMM ----------------
__global__ __launch_bounds__(512, 1)
void cp2d_fp16_kernel(const float* __restrict__ x, float* __restrict__ out) {
    extern __shared__ __align__(128) char smem[];
    const uint32_t sb = smem_u32(smem);

    const int tid  = threadIdx.x;
    const int lane = tid & 31;
    const int warp = tid >> 5;
    const int wm   = warp & 3;          // 4 warps along M
    const int wn   = warp >> 2;         // 4 warps along N
    const long m0  = (long)blockIdx.x * BM;

    // A global-load / STS mapping: 128 rows x 16 float4 per chunk, 4/thread
    const int a_f   = tid & 15;         // float4 index along k
    const int a_row = tid >> 4;         // base row (0..31), rows += j*32
    // B cp.async mapping: 256 rows x 8 x 16B per chunk, 4/thread
    const int b_u   = tid & 7;
    const int b_row = tid >> 3;         // base row (0..63), rows += j*64

    // ldmatrix per-lane invariants
    const int la_row = (lane & 7) + ((lane >> 3) & 1) * 8;   // A: 0..15
    const int la_u   = lane >> 4;
    const int lb_row = (lane & 7) + ((lane >> 4) & 1) * 8;   // B: 0..15
    const int lb_u   = (lane >> 3) & 1;

    float acc[2][8][4];
#pragma unroll
    for (int mt = 0; mt < 2; mt++)
#pragma unroll
        for (int nt = 0; nt < 8; nt++)
#pragma unroll
            for (int i = 0; i < 4; i++) acc[mt][nt][i] = 0.f;

    float4 rA[4];

    auto ldgA = [&](int c) {
#pragma unroll
        for (int j = 0; j < 4; j++)
            rA[j] = *(const float4*)(x + (m0 + a_row + j * 32) * KDIM + c * BK + a_f * 4);
    };
    auto stsA = [&](int st) {
        const uint32_t aBase = sb + st * A_STAGE_BYTES;
        const int u = a_f >> 1, off8 = (a_f & 1) * 8;
#pragma unroll
        for (int j = 0; j < 4; j++) {
            const int row = a_row + j * 32;
            uint32_t addr = aBase + row * 128 + ((u ^ (row & 7)) << 4) + off8;
            __half2 h0 = __floats2half2_rn(rA[j].x, rA[j].y);
            __half2 h1 = __floats2half2_rn(rA[j].z, rA[j].w);
            asm volatile("st.shared.v2.b32 [%0], {%1, %2};"
                         :: "r"(addr), "r"(*(uint32_t*)&h0), "r"(*(uint32_t*)&h1));
        }
    };
    auto cpB = [&](int c) {
        const uint32_t bBase = sb + A_TOTAL + (uint32_t)c * B_CHUNK_BYTES;
#pragma unroll
        for (int j = 0; j < 4; j++) {
            const int row = b_row + j * 64;
            uint32_t dst = bBase + row * 128 + ((b_u ^ (row & 7)) << 4);
            cp16(dst, g_Wt + row * KDIM + c * BK + b_u * 8);
        }
        cp_commit();
    };

    auto compute = [&](int st, int cb) {
        const uint32_t aBase = sb + st * A_STAGE_BYTES;
        const uint32_t bBase = sb + A_TOTAL + (uint32_t)cb * B_CHUNK_BYTES;
#pragma unroll
        for (int ks = 0; ks < 4; ks++) {
            const int u0 = ks * 2;
            uint32_t a[2][4];
#pragma unroll
            for (int mt = 0; mt < 2; mt++) {
                const int row = wm * 32 + mt * 16 + la_row;
                uint32_t addr = aBase + row * 128 + (((u0 + la_u) ^ (row & 7)) << 4);
                LDSM4(a[mt][0], a[mt][1], a[mt][2], a[mt][3], addr);
            }
            uint32_t b[4][4];
#pragma unroll
            for (int nt2 = 0; nt2 < 4; nt2++) {
                const int row = wn * 64 + nt2 * 16 + lb_row;
                uint32_t addr = bBase + row * 128 + (((u0 + lb_u) ^ (row & 7)) << 4);
                LDSM4(b[nt2][0], b[nt2][1], b[nt2][2], b[nt2][3], addr);
            }
#pragma unroll
            for (int nt2 = 0; nt2 < 4; nt2++)
#pragma unroll
                for (int s = 0; s < 2; s++) {
                    const int nt = nt2 * 2 + s;
                    mma_fp16(acc[0][nt], a[0], b[nt2][2 * s], b[nt2][2 * s + 1]);
                    mma_fp16(acc[1][nt], a[1], b[nt2][2 * s], b[nt2][2 * s + 1]);
                }
        }
    };

    // ---- prologue ----
    ldgA(0);
    cpB(0); cpB(1); cpB(2); cpB(3);     // 4 groups, completion tracked per chunk
    stsA(0);
    ldgA(1);
    cp_wait<3>();            // B chunk 0 landed (this thread's copies)
    __syncthreads();         // A stage0 stores + everyone's B0 visible

    // ---- main loop: one barrier per chunk ----
    // c=0
    stsA(1); ldgA(2);
    compute(0, 0);
    cp_wait<2>(); __syncthreads();      // B1 + A stage1 ready
    // c=1
    stsA(0); ldgA(3);
    compute(1, 1);
    cp_wait<1>(); __syncthreads();      // B2 + A stage0 ready
    // c=2
    stsA(1);
    compute(0, 2);
    cp_wait<0>(); __syncthreads();      // B3 + A stage1 ready
    // c=3
    compute(1, 3);

    // ---- epilogue: direct STG from accumulators ----
    const int er = lane >> 2;
    const int ec = (lane & 3) * 2;
#pragma unroll
    for (int mt = 0; mt < 2; mt++) {
        const long r0 = m0 + wm * 32 + mt * 16 + er;
#pragma unroll
        for (int nt = 0; nt < 8; nt++) {
            const int col = wn * 64 + nt * 8 + ec;
            *(float2*)(out + r0 * KDIM + col) =
                make_float2(acc[mt][nt][0], acc[mt][nt][1]);
            *(float2*)(out + (r0 + 8) * KDIM + col) =
                make_float2(acc[mt][nt][2], acc[mt][nt][3]);
        }
    }
}

extern "C" void kernel_launch(void* const* d_in, const int* in_sizes, int n_in,
                              void* d_out, int out_size) {
    const float* x = (const float*)d_in[0];
    const float* W = (const float*)d_in[1];
    float* out = (float*)d_out;

    const int M = in_sizes[0] / KDIM;   // 401408

    cudaFuncSetAttribute(cp2d_fp16_kernel,
                         cudaFuncAttributeMaxDynamicSharedMemorySize, SMEM_TOTAL);

    prep_wt_kernel<<<KDIM, KDIM>>>(W);
    cp2d_fp16_kernel<<<M / BM, 512, SMEM_TOTAL>>>(x, out);
}

// round 6
// speedup vs baseline: 1.0902x; 1.0902x over previous
#include <cuda_runtime.h>
#include <cuda_fp16.h>
#include <cstdint>

#define KDIM   256
#define BM     64
#define BN     256
#define BK     64
#define NCHUNK 4

#define A_STAGE_BYTES (BM * BK * 2)            // 8192
#define B_STAGE_BYTES (BN * BK * 2)            // 32768
#define STAGE_BYTES   (A_STAGE_BYTES + B_STAGE_BYTES)   // 40960
#define SMEM_TOTAL    (2 * STAGE_BYTES)        // 81920

// W^T in fp16: g_Wt[n][k] = half(W[k][n])
__device__ __align__(256) __half g_Wt[KDIM * KDIM];

// ---------------- helpers ----------------
__device__ __forceinline__ uint32_t smem_u32(const void* p) {
    uint32_t a;
    asm("{ .reg .u64 t; cvta.to.shared.u64 t, %1; cvt.u32.u64 %0, t; }" : "=r"(a) : "l"(p));
    return a;
}
__device__ __forceinline__ void cp16(uint32_t dst, const void* src) {
    asm volatile("cp.async.cg.shared.global [%0], [%1], 16;" :: "r"(dst), "l"(src));
}
__device__ __forceinline__ void cp_commit() {
    asm volatile("cp.async.commit_group;" ::: "memory");
}
template <int N> __device__ __forceinline__ void cp_wait() {
    asm volatile("cp.async.wait_group %0;" :: "n"(N) : "memory");
}
#define LDSM4(r0, r1, r2, r3, a)                                                 \
    asm volatile("ldmatrix.sync.aligned.m8n8.x4.shared.b16 {%0,%1,%2,%3}, [%4];" \
                 : "=r"(r0), "=r"(r1), "=r"(r2), "=r"(r3) : "r"(a))

__device__ __forceinline__ void mma_fp16(float* d, const uint32_t* a,
                                         uint32_t b0, uint32_t b1) {
    asm volatile(
        "mma.sync.aligned.m16n8k16.row.col.f32.f16.f16.f32 "
        "{%0,%1,%2,%3}, {%4,%5,%6,%7}, {%8,%9}, {%0,%1,%2,%3};"
        : "+f"(d[0]), "+f"(d[1]), "+f"(d[2]), "+f"(d[3])
        : "r"(a[0]), "r"(a[1]), "r"(a[2]), "r"(a[3]), "r"(b0), "r"(b1));
}

// ---------------- prep: W[K,N] fp32 -> Wt[N,K] fp16 ----------------
__global__ void prep_wt_kernel(const float* __restrict__ W) {
    int n = blockIdx.x, k = threadIdx.x;
    g_Wt[n * KDIM + k] = __float2half_rn(W[k * KDIM + n]);
}

// ---------------- main GEMM ----------------
__global__ __launch_bounds__(256, 2)
void cp2d_fp16_kernel(const float* __restrict__ x, float* __restrict__ out) {
    extern __shared__ __align__(128) char smem[];
    const uint32_t sb = smem_u32(smem);

    const int tid  = threadIdx.x;
    const int lane = tid & 31;
    const int warp = tid >> 5;
    const int wm   = warp & 1;          // 2 warps along M (32 rows each)
    const int wn   = warp >> 1;         // 4 warps along N (64 cols each)
    const long m0  = (long)blockIdx.x * BM;

    // A global-load / STS mapping: 64 rows x 16 float4 per chunk, 4/thread
    const int a_f   = tid & 15;         // float4 index along k
    const int a_row = tid >> 4;         // base row (0..15), rows += j*16
    // B cp.async mapping: 256 rows x 8 x 16B per chunk, 8/thread
    const int b_u   = tid & 7;
    const int b_row = tid >> 3;         // base row (0..31), rows += j*32

    // ldmatrix per-lane invariants
    const int la_row = (lane & 7) + ((lane >> 3) & 1) * 8;   // A: 0..15
    const int la_u   = lane >> 4;
    const int lb_row = (lane & 7) + ((lane >> 4) & 1) * 8;   // B: 0..15
    const int lb_u   = (lane >> 3) & 1;

    float acc[2][8][4];
#pragma unroll
    for (int mt = 0; mt < 2; mt++)
#pragma unroll
        for (int nt = 0; nt < 8; nt++)
#pragma unroll
            for (int i = 0; i < 4; i++) acc[mt][nt][i] = 0.f;

    float4 rA[4];

    auto ldgA = [&](int c) {
#pragma unroll
        for (int j = 0; j < 4; j++)
            rA[j] = *(const float4*)(x + (m0 + a_row + j * 16) * KDIM + c * BK + a_f * 4);
    };
    auto stsA = [&](int st) {          // st MUST be 0 or 1 (stage index)
        const uint32_t aBase = sb + (uint32_t)st * STAGE_BYTES;
        const int u = a_f >> 1, off8 = (a_f & 1) * 8;
#pragma unroll
        for (int j = 0; j < 4; j++) {
            const int row = a_row + j * 16;
            uint32_t addr = aBase + row * 128 + ((u ^ (row & 7)) << 4) + off8;
            __half2 h0 = __floats2half2_rn(rA[j].x, rA[j].y);
            __half2 h1 = __floats2half2_rn(rA[j].z, rA[j].w);
            asm volatile("st.shared.v2.b32 [%0], {%1, %2};"
                         :: "r"(addr), "r"(*(uint32_t*)&h0), "r"(*(uint32_t*)&h1));
        }
    };
    auto cpB = [&](int c) {
        const uint32_t bBase = sb + (uint32_t)(c & 1) * STAGE_BYTES + A_STAGE_BYTES;
#pragma unroll
        for (int j = 0; j < 8; j++) {
            const int row = b_row + j * 32;
            uint32_t dst = bBase + row * 128 + ((b_u ^ (row & 7)) << 4);
            cp16(dst, g_Wt + row * KDIM + c * BK + b_u * 8);
        }
        cp_commit();
    };

    auto compute = [&](int c) {
        const uint32_t aBase = sb + (uint32_t)(c & 1) * STAGE_BYTES;
        const uint32_t bBase = aBase + A_STAGE_BYTES;
#pragma unroll
        for (int ks = 0; ks < 4; ks++) {
            const int u0 = ks * 2;
            uint32_t a[2][4];
#pragma unroll
            for (int mt = 0; mt < 2; mt++) {
                const int row = wm * 32 + mt * 16 + la_row;
                uint32_t addr = aBase + row * 128 + (((u0 + la_u) ^ (row & 7)) << 4);
                LDSM4(a[mt][0], a[mt][1], a[mt][2], a[mt][3], addr);
            }
            uint32_t b[4][4];
#pragma unroll
            for (int nt2 = 0; nt2 < 4; nt2++) {
                const int row = wn * 64 + nt2 * 16 + lb_row;
                uint32_t addr = bBase + row * 128 + (((u0 + lb_u) ^ (row & 7)) << 4);
                LDSM4(b[nt2][0], b[nt2][1], b[nt2][2], b[nt2][3], addr);
            }
#pragma unroll
            for (int nt2 = 0; nt2 < 4; nt2++)
#pragma unroll
                for (int s = 0; s < 2; s++) {
                    const int nt = nt2 * 2 + s;
                    mma_fp16(acc[0][nt], a[0], b[nt2][2 * s], b[nt2][2 * s + 1]);
                    mma_fp16(acc[1][nt], a[1], b[nt2][2 * s], b[nt2][2 * s + 1]);
                }
        }
    };

    // ---- prologue: chunk 0 fully staged ----
    ldgA(0);
    cpB(0);
    stsA(0);
    ldgA(1);
    cp_wait<0>();
    __syncthreads();         // stage0 (A stores + B0) visible to all

    // ---- main loop: prefetch chunk c+1 into other stage, then compute(c) ----
#pragma unroll
    for (int c = 0; c < NCHUNK; c++) {
        if (c + 1 < NCHUNK) {
            stsA((c + 1) & 1);           // rA holds chunk c+1 -> stage (c+1)&1
            if (c + 2 < NCHUNK) ldgA(c + 2);
            cpB(c + 1);
        }
        compute(c);
        if (c + 1 < NCHUNK) {
            cp_wait<0>();
            __syncthreads();             // stage (c+1)&1 fully ready
        }
    }

    // ---- epilogue: direct STG from accumulators ----
    const int er = lane >> 2;
    const int ec = (lane & 3) * 2;
#pragma unroll
    for (int mt = 0; mt < 2; mt++) {
        const long r0 = m0 + wm * 32 + mt * 16 + er;
#pragma unroll
        for (int nt = 0; nt < 8; nt++) {
            const int col = wn * 64 + nt * 8 + ec;
            *(float2*)(out + r0 * KDIM + col) =
                make_float2(acc[mt][nt][0], acc[mt][nt][1]);
            *(float2*)(out + (r0 + 8) * KDIM + col) =
                make_float2(acc[mt][nt][2], acc[mt][nt][3]);
        }
    }
}

extern "C" void kernel_launch(void* const* d_in, const int* in_sizes, int n_in,
                              void* d_out, int out_size) {
    const float* x = (const float*)d_in[0];
    const float* W = (const float*)d_in[1];
    float* out = (float*)d_out;

    const int M = in_sizes[0] / KDIM;   // 401408

    cudaFuncSetAttribute(cp2d_fp16_kernel,
                         cudaFuncAttributeMaxDynamicSharedMemorySize, SMEM_TOTAL);

    prep_wt_kernel<<<KDIM, KDIM>>>(W);
    cp2d_fp16_kernel<<<M / BM, 256, SMEM_TOTAL>>>(x, out);
}

// round 7
// speedup vs baseline: 1.2804x; 1.1745x over previous
#include <cuda_runtime.h>
#include <cuda_fp16.h>
#include <cstdint>

#define KDIM   256
#define BM     128
#define BN     256
#define BK     64

#define A_STAGE_BYTES (BM * BK * 2)            // 16384
#define A_TOTAL       (2 * A_STAGE_BYTES)      // 32768
#define B_CHUNK_BYTES (BN * BK * 2)            // 32768
#define B_TOTAL       (4 * B_CHUNK_BYTES)      // 131072
#define SMEM_TOTAL    (A_TOTAL + B_TOTAL)      // 163840

// W^T in fp16: g_Wt[n][k] = half(W[k][n])
__device__ __align__(256) __half g_Wt[KDIM * KDIM];

// ---------------- helpers ----------------
__device__ __forceinline__ uint32_t smem_u32(const void* p) {
    uint32_t a;
    asm("{ .reg .u64 t; cvta.to.shared.u64 t, %1; cvt.u32.u64 %0, t; }" : "=r"(a) : "l"(p));
    return a;
}
__device__ __forceinline__ void cp16(uint32_t dst, const void* src) {
    asm volatile("cp.async.cg.shared.global [%0], [%1], 16;" :: "r"(dst), "l"(src));
}
__device__ __forceinline__ void cp_commit() {
    asm volatile("cp.async.commit_group;" ::: "memory");
}
template <int N> __device__ __forceinline__ void cp_wait() {
    asm volatile("cp.async.wait_group %0;" :: "n"(N) : "memory");
}
#define LDSM4(r0, r1, r2, r3, a)                                                 \
    asm volatile("ldmatrix.sync.aligned.m8n8.x4.shared.b16 {%0,%1,%2,%3}, [%4];" \
                 : "=r"(r0), "=r"(r1), "=r"(r2), "=r"(r3) : "r"(a))

__device__ __forceinline__ void mma_fp16(float* d, const uint32_t* a,
                                         uint32_t b0, uint32_t b1) {
    asm volatile(
        "mma.sync.aligned.m16n8k16.row.col.f32.f16.f16.f32 "
        "{%0,%1,%2,%3}, {%4,%5,%6,%7}, {%8,%9}, {%0,%1,%2,%3};"
        : "+f"(d[0]), "+f"(d[1]), "+f"(d[2]), "+f"(d[3])
        : "r"(a[0]), "r"(a[1]), "r"(a[2]), "r"(a[3]), "r"(b0), "r"(b1));
}

// ---------------- prep: W[K,N] fp32 -> Wt[N,K] fp16 ----------------
__global__ void prep_wt_kernel(const float* __restrict__ W) {
    int n = blockIdx.x, k = threadIdx.x;
    g_Wt[n * KDIM + k] = __float2half_rn(W[k * KDIM + n]);
}

// ---------------- main GEMM: persistent CTAs, B resident ----------------
__global__ __launch_bounds__(512, 1)
void cp2d_fp16_kernel(const float* __restrict__ x, float* __restrict__ out,
                      int G, int NT) {
    extern __shared__ __align__(128) char smem[];
    const uint32_t sb = smem_u32(smem);

    const int tid  = threadIdx.x;
    const int lane = tid & 31;
    const int warp = tid >> 5;
    const int wm   = warp & 3;          // 4 warps along M (32 rows)
    const int wn   = warp >> 2;         // 4 warps along N (64 cols)
    const int bid  = blockIdx.x;

    const int my_tiles = (NT - bid + G - 1) / G;   // tiles: bid, bid+G, ...
    if (my_tiles <= 0) return;
    const int GG = my_tiles * 4;                   // total chunk stream length

    // A mapping: 128 rows x 16 float4, 4/thread
    const int a_f   = tid & 15;
    const int a_row = tid >> 4;         // 0..31, rows += j*32
    // B mapping: 256 rows x 8 x 16B per chunk, 4/thread/chunk
    const int b_u   = tid & 7;
    const int b_row = tid >> 3;         // 0..63, rows += j*64

    // ldmatrix per-lane invariants
    const int la_row = (lane & 7) + ((lane >> 3) & 1) * 8;
    const int la_u   = lane >> 4;
    const int lb_row = (lane & 7) + ((lane >> 4) & 1) * 8;
    const int lb_u   = (lane >> 3) & 1;

    float acc[2][8][4];
#pragma unroll
    for (int mt = 0; mt < 2; mt++)
#pragma unroll
        for (int nt = 0; nt < 8; nt++)
#pragma unroll
            for (int i = 0; i < 4; i++) acc[mt][nt][i] = 0.f;

    float4 rA[4];

    // tile row base for chunk-stream index gg
    auto m_of = [&](int gg) -> long {
        return ((long)bid + (long)(gg >> 2) * G) * BM;
    };
    auto ldgA = [&](int gg) {
        const long m0 = m_of(gg);
        const int k0 = (gg & 3) * BK;
#pragma unroll
        for (int j = 0; j < 4; j++)
            rA[j] = *(const float4*)(x + (m0 + a_row + j * 32) * KDIM + k0 + a_f * 4);
    };
    auto stsA = [&](int st) {          // st = 0/1
        const uint32_t aBase = sb + (uint32_t)st * A_STAGE_BYTES;
        const int u = a_f >> 1, off8 = (a_f & 1) * 8;
#pragma unroll
        for (int j = 0; j < 4; j++) {
            const int row = a_row + j * 32;
            uint32_t addr = aBase + row * 128 + ((u ^ (row & 7)) << 4) + off8;
            __half2 h0 = __floats2half2_rn(rA[j].x, rA[j].y);
            __half2 h1 = __floats2half2_rn(rA[j].z, rA[j].w);
            asm volatile("st.shared.v2.b32 [%0], {%1, %2};"
                         :: "r"(addr), "r"(*(uint32_t*)&h0), "r"(*(uint32_t*)&h1));
        }
    };

    auto compute = [&](int st, int cb) {
        const uint32_t aBase = sb + (uint32_t)st * A_STAGE_BYTES;
        const uint32_t bBase = sb + A_TOTAL + (uint32_t)cb * B_CHUNK_BYTES;
#pragma unroll
        for (int ks = 0; ks < 4; ks++) {
            const int u0 = ks * 2;
            uint32_t a[2][4];
#pragma unroll
            for (int mt = 0; mt < 2; mt++) {
                const int row = wm * 32 + mt * 16 + la_row;
                uint32_t addr = aBase + row * 128 + (((u0 + la_u) ^ (row & 7)) << 4);
                LDSM4(a[mt][0], a[mt][1], a[mt][2], a[mt][3], addr);
            }
            uint32_t b[4][4];
#pragma unroll
            for (int nt2 = 0; nt2 < 4; nt2++) {
                const int row = wn * 64 + nt2 * 16 + lb_row;
                uint32_t addr = bBase + row * 128 + (((u0 + lb_u) ^ (row & 7)) << 4);
                LDSM4(b[nt2][0], b[nt2][1], b[nt2][2], b[nt2][3], addr);
            }
#pragma unroll
            for (int nt2 = 0; nt2 < 4; nt2++)
#pragma unroll
                for (int s = 0; s < 2; s++) {
                    const int nt = nt2 * 2 + s;
                    mma_fp16(acc[0][nt], a[0], b[nt2][2 * s], b[nt2][2 * s + 1]);
                    mma_fp16(acc[1][nt], a[1], b[nt2][2 * s], b[nt2][2 * s + 1]);
                }
        }
    };

    // ---- prologue: load entire B once; stage A chunk 0 ----
#pragma unroll
    for (int c = 0; c < 4; c++) {
        const uint32_t bBase = sb + A_TOTAL + (uint32_t)c * B_CHUNK_BYTES;
#pragma unroll
        for (int j = 0; j < 4; j++) {
            const int row = b_row + j * 64;
            uint32_t dst = bBase + row * 128 + ((b_u ^ (row & 7)) << 4);
            cp16(dst, g_Wt + row * KDIM + c * BK + b_u * 8);
        }
    }
    cp_commit();
    ldgA(0);
    cp_wait<0>();            // B fully resident
    stsA(0);
    if (GG > 1) ldgA(1);
    __syncthreads();         // B + A stage0 visible

    // ---- unified chunk stream across all tiles ----
    for (int gg = 0; gg < GG; gg++) {
        const int st = gg & 1;
        if (gg + 1 < GG) {
            stsA(st ^ 1);                    // rA holds chunk gg+1
            if (gg + 2 < GG) ldgA(gg + 2);
        }
        compute(st, gg & 3);

        if ((gg & 3) == 3) {
            // epilogue for this tile (regs only, overlaps prefetched loads)
            const long m0 = m_of(gg);
            const int er = lane >> 2;
            const int ec = (lane & 3) * 2;
#pragma unroll
            for (int mt = 0; mt < 2; mt++) {
                const long r0 = m0 + wm * 32 + mt * 16 + er;
#pragma unroll
                for (int nt = 0; nt < 8; nt++) {
                    const int col = wn * 64 + nt * 8 + ec;
                    *(float2*)(out + r0 * KDIM + col) =
                        make_float2(acc[mt][nt][0], acc[mt][nt][1]);
                    *(float2*)(out + (r0 + 8) * KDIM + col) =
                        make_float2(acc[mt][nt][2], acc[mt][nt][3]);
                }
            }
#pragma unroll
            for (int mt = 0; mt < 2; mt++)
#pragma unroll
                for (int nt = 0; nt < 8; nt++)
#pragma unroll
                    for (int i = 0; i < 4; i++) acc[mt][nt][i] = 0.f;
        }
        if (gg + 1 < GG) __syncthreads();    // stage (gg+1)&1 ready / WAR guard
    }
}

extern "C" void kernel_launch(void* const* d_in, const int* in_sizes, int n_in,
                              void* d_out, int out_size) {
    const float* x = (const float*)d_in[0];
    const float* W = (const float*)d_in[1];
    float* out = (float*)d_out;

    const int M  = in_sizes[0] / KDIM;   // 401408
    const int NT = M / BM;               // 3136 tiles

    int nsm = 0;
    cudaDeviceGetAttribute(&nsm, cudaDevAttrMultiProcessorCount, 0);
    if (nsm <= 0) nsm = 148;
    if (nsm > NT) nsm = NT;

    cudaFuncSetAttribute(cp2d_fp16_kernel,
                         cudaFuncAttributeMaxDynamicSharedMemorySize, SMEM_TOTAL);

    prep_wt_kernel<<<KDIM, KDIM>>>(W);
    cp2d_fp16_kernel<<<nsm, 512, SMEM_TOTAL>>>(x, out, nsm, NT);
}

// round 8
// speedup vs baseline: 1.3150x; 1.0270x over previous
#include <cuda_runtime.h>
#include <cuda_fp16.h>
#include <cstdint>

#define KDIM   256
#define BM     128
#define BN     256
#define BK     64

#define A_STAGE_BYTES (BM * BK * 2)            // 16384
#define A_TOTAL       (2 * A_STAGE_BYTES)      // 32768
#define B_CHUNK_BYTES (BN * BK * 2)            // 32768
#define B_TOTAL       (4 * B_CHUNK_BYTES)      // 131072
#define SMEM_TOTAL    (A_TOTAL + B_TOTAL)      // 163840

// W^T in fp16: g_Wt[n][k] = half(W[k][n])
__device__ __align__(256) __half g_Wt[KDIM * KDIM];

// ---------------- helpers ----------------
__device__ __forceinline__ uint32_t smem_u32(const void* p) {
    uint32_t a;
    asm("{ .reg .u64 t; cvta.to.shared.u64 t, %1; cvt.u32.u64 %0, t; }" : "=r"(a) : "l"(p));
    return a;
}
__device__ __forceinline__ void cp16(uint32_t dst, const void* src) {
    asm volatile("cp.async.cg.shared.global [%0], [%1], 16;" :: "r"(dst), "l"(src));
}
__device__ __forceinline__ void cp_commit() {
    asm volatile("cp.async.commit_group;" ::: "memory");
}
template <int N> __device__ __forceinline__ void cp_wait() {
    asm volatile("cp.async.wait_group %0;" :: "n"(N) : "memory");
}
#define LDSM4(r0, r1, r2, r3, a)                                                 \
    asm volatile("ldmatrix.sync.aligned.m8n8.x4.shared.b16 {%0,%1,%2,%3}, [%4];" \
                 : "=r"(r0), "=r"(r1), "=r"(r2), "=r"(r3) : "r"(a))

__device__ __forceinline__ void mma_fp16(float* d, const uint32_t* a,
                                         uint32_t b0, uint32_t b1) {
    asm volatile(
        "mma.sync.aligned.m16n8k16.row.col.f32.f16.f16.f32 "
        "{%0,%1,%2,%3}, {%4,%5,%6,%7}, {%8,%9}, {%0,%1,%2,%3};"
        : "+f"(d[0]), "+f"(d[1]), "+f"(d[2]), "+f"(d[3])
        : "r"(a[0]), "r"(a[1]), "r"(a[2]), "r"(a[3]), "r"(b0), "r"(b1));
}

// ---------------- prep: W[K,N] fp32 -> Wt[N,K] fp16 ----------------
__global__ void prep_wt_kernel(const float* __restrict__ W) {
    int n = blockIdx.x, k = threadIdx.x;
    g_Wt[n * KDIM + k] = __float2half_rn(W[k * KDIM + n]);
}

// ---------------- main GEMM: persistent CTAs, B resident, 64x64 warp tile ----------------
__global__ __launch_bounds__(256, 1)
void cp2d_fp16_kernel(const float* __restrict__ x, float* __restrict__ out,
                      int G, int NT) {
    extern __shared__ __align__(128) char smem[];
    const uint32_t sb = smem_u32(smem);

    const int tid  = threadIdx.x;
    const int lane = tid & 31;
    const int warp = tid >> 5;
    const int wm   = warp & 1;          // 2 warps along M (64 rows each)
    const int wn   = warp >> 1;         // 4 warps along N (64 cols each)
    const int bid  = blockIdx.x;

    const int my_tiles = (NT - bid + G - 1) / G;   // tiles: bid, bid+G, ...
    if (my_tiles <= 0) return;
    const int GG = my_tiles * 4;

    // A mapping: 128 rows x 16 float4 per chunk, 8/thread
    const int a_f   = tid & 15;
    const int a_row = tid >> 4;         // 0..15, rows += j*16
    // B mapping: 256 rows x 8 x 16B per chunk, 8/thread/chunk
    const int b_u   = tid & 7;
    const int b_row = tid >> 3;         // 0..31, rows += j*32

    // ldmatrix per-lane invariants
    const int la_row = (lane & 7) + ((lane >> 3) & 1) * 8;
    const int la_u   = lane >> 4;
    const int lb_row = (lane & 7) + ((lane >> 4) & 1) * 8;
    const int lb_u   = (lane >> 3) & 1;

    float acc[4][8][4];
#pragma unroll
    for (int mt = 0; mt < 4; mt++)
#pragma unroll
        for (int nt = 0; nt < 8; nt++)
#pragma unroll
            for (int i = 0; i < 4; i++) acc[mt][nt][i] = 0.f;

    float4 rA[8];

    auto m_of = [&](int gg) -> long {
        return ((long)bid + (long)(gg >> 2) * G) * BM;
    };
    auto ldgA = [&](int gg) {
        const long m0 = m_of(gg);
        const int k0 = (gg & 3) * BK;
#pragma unroll
        for (int j = 0; j < 8; j++)
            rA[j] = *(const float4*)(x + (m0 + a_row + j * 16) * KDIM + k0 + a_f * 4);
    };
    auto stsA = [&](int st) {          // st = 0/1
        const uint32_t aBase = sb + (uint32_t)st * A_STAGE_BYTES;
        const int u = a_f >> 1, off8 = (a_f & 1) * 8;
#pragma unroll
        for (int j = 0; j < 8; j++) {
            const int row = a_row + j * 16;
            uint32_t addr = aBase + row * 128 + ((u ^ (row & 7)) << 4) + off8;
            __half2 h0 = __floats2half2_rn(rA[j].x, rA[j].y);
            __half2 h1 = __floats2half2_rn(rA[j].z, rA[j].w);
            asm volatile("st.shared.v2.b32 [%0], {%1, %2};"
                         :: "r"(addr), "r"(*(uint32_t*)&h0), "r"(*(uint32_t*)&h1));
        }
    };

    auto compute = [&](int st, int cb) {
        const uint32_t aBase = sb + (uint32_t)st * A_STAGE_BYTES;
        const uint32_t bBase = sb + A_TOTAL + (uint32_t)cb * B_CHUNK_BYTES;
#pragma unroll
        for (int ks = 0; ks < 4; ks++) {
            const int u0 = ks * 2;
            uint32_t b[4][4];
#pragma unroll
            for (int nt2 = 0; nt2 < 4; nt2++) {
                const int row = wn * 64 + nt2 * 16 + lb_row;
                uint32_t addr = bBase + row * 128 + (((u0 + lb_u) ^ (row & 7)) << 4);
                LDSM4(b[nt2][0], b[nt2][1], b[nt2][2], b[nt2][3], addr);
            }
#pragma unroll
            for (int mt = 0; mt < 4; mt++) {
                uint32_t a[4];
                const int row = wm * 64 + mt * 16 + la_row;
                uint32_t addr = aBase + row * 128 + (((u0 + la_u) ^ (row & 7)) << 4);
                LDSM4(a[0], a[1], a[2], a[3], addr);
#pragma unroll
                for (int nt2 = 0; nt2 < 4; nt2++)
#pragma unroll
                    for (int s = 0; s < 2; s++) {
                        const int nt = nt2 * 2 + s;
                        mma_fp16(acc[mt][nt], a, b[nt2][2 * s], b[nt2][2 * s + 1]);
                    }
            }
        }
    };

    // ---- prologue: load entire B once; stage A chunk 0 ----
#pragma unroll
    for (int c = 0; c < 4; c++) {
        const uint32_t bBase = sb + A_TOTAL + (uint32_t)c * B_CHUNK_BYTES;
#pragma unroll
        for (int j = 0; j < 8; j++) {
            const int row = b_row + j * 32;
            uint32_t dst = bBase + row * 128 + ((b_u ^ (row & 7)) << 4);
            cp16(dst, g_Wt + row * KDIM + c * BK + b_u * 8);
        }
    }
    cp_commit();
    ldgA(0);
    cp_wait<0>();            // B fully resident
    stsA(0);
    if (GG > 1) ldgA(1);
    __syncthreads();         // B + A stage0 visible

    // ---- unified chunk stream across all tiles ----
    for (int gg = 0; gg < GG; gg++) {
        const int st = gg & 1;
        if (gg + 1 < GG) {
            stsA(st ^ 1);                    // rA holds chunk gg+1
            if (gg + 2 < GG) ldgA(gg + 2);
        }
        compute(st, gg & 3);

        if ((gg & 3) == 3) {
            const long m0 = m_of(gg);
            const int er = lane >> 2;
            const int ec = (lane & 3) * 2;
#pragma unroll
            for (int mt = 0; mt < 4; mt++) {
                const long r0 = m0 + wm * 64 + mt * 16 + er;
#pragma unroll
                for (int nt = 0; nt < 8; nt++) {
                    const int col = wn * 64 + nt * 8 + ec;
                    *(float2*)(out + r0 * KDIM + col) =
                        make_float2(acc[mt][nt][0], acc[mt][nt][1]);
                    *(float2*)(out + (r0 + 8) * KDIM + col) =
                        make_float2(acc[mt][nt][2], acc[mt][nt][3]);
                }
            }
#pragma unroll
            for (int mt = 0; mt < 4; mt++)
#pragma unroll
                for (int nt = 0; nt < 8; nt++)
#pragma unroll
                    for (int i = 0; i < 4; i++) acc[mt][nt][i] = 0.f;
        }
        if (gg + 1 < GG) __syncthreads();    // stage (gg+1)&1 ready / WAR guard
    }
}

extern "C" void kernel_launch(void* const* d_in, const int* in_sizes, int n_in,
                              void* d_out, int out_size) {
    const float* x = (const float*)d_in[0];
    const float* W = (const float*)d_in[1];
    float* out = (float*)d_out;

    const int M  = in_sizes[0] / KDIM;   // 401408
    const int NT = M / BM;               // 3136 tiles

    int nsm = 0;
    cudaDeviceGetAttribute(&nsm, cudaDevAttrMultiProcessorCount, 0);
    if (nsm <= 0) nsm = 148;
    if (nsm > NT) nsm = NT;

    cudaFuncSetAttribute(cp2d_fp16_kernel,
                         cudaFuncAttributeMaxDynamicSharedMemorySize, SMEM_TOTAL);

    prep_wt_kernel<<<KDIM, KDIM>>>(W);
    cp2d_fp16_kernel<<<nsm, 256, SMEM_TOTAL>>>(x, out, nsm, NT);
}